// round 1
// baseline (speedup 1.0000x reference)
#include <cuda_runtime.h>

// ============================================================================
// Clebsch-Gordan tensor product, MAXL=5, TAUS=16, BATCH=256.
//
// 69 triples (l1,l2,l) in reference loop order. Output per l:
//   (256, 256*cnt_l, 2l+1, 2) fp32, concatenated l=0..5 -> 59,899,904 floats.
//
// Strategy: one main kernel, grid=(256 batches, 69 fragments), 256 threads =
// 16x16 channel pairs. Templated per-triple body (all loops fully unrolled,
// operands in registers), outputs staged in SMEM for coalesced stores.
// CG coefficients built exactly (fp64, exact factorial literals) by a tiny
// init kernel each launch (graph-capturable, deterministic, allocation-free).
// ============================================================================

#define NFRAG 69

// X-macro: (frag_id, l1, l2, l) in exact reference _TRIPLES order
#define FRAGS(X) \
X(0,0,0,0) X(1,1,0,1) X(2,1,1,0) X(3,1,1,1) X(4,1,1,2) \
X(5,2,0,2) X(6,2,1,1) X(7,2,1,2) X(8,2,1,3) \
X(9,2,2,0) X(10,2,2,1) X(11,2,2,2) X(12,2,2,3) X(13,2,2,4) \
X(14,3,0,3) X(15,3,1,2) X(16,3,1,3) X(17,3,1,4) \
X(18,3,2,1) X(19,3,2,2) X(20,3,2,3) X(21,3,2,4) X(22,3,2,5) \
X(23,3,3,0) X(24,3,3,1) X(25,3,3,2) X(26,3,3,3) X(27,3,3,4) X(28,3,3,5) \
X(29,4,0,4) X(30,4,1,3) X(31,4,1,4) X(32,4,1,5) \
X(33,4,2,2) X(34,4,2,3) X(35,4,2,4) X(36,4,2,5) \
X(37,4,3,1) X(38,4,3,2) X(39,4,3,3) X(40,4,3,4) X(41,4,3,5) \
X(42,4,4,0) X(43,4,4,1) X(44,4,4,2) X(45,4,4,3) X(46,4,4,4) X(47,4,4,5) \
X(48,5,0,5) X(49,5,1,4) X(50,5,1,5) \
X(51,5,2,3) X(52,5,2,4) X(53,5,2,5) \
X(54,5,3,2) X(55,5,3,3) X(56,5,3,4) X(57,5,3,5) \
X(58,5,4,1) X(59,5,4,2) X(60,5,4,3) X(61,5,4,4) X(62,5,4,5) \
X(63,5,5,0) X(64,5,5,1) X(65,5,5,2) X(66,5,5,3) X(67,5,5,4) X(68,5,5,5)

struct Meta {
    int out_base[NFRAG];   // float2 offset of out[l] section start
    int chan_off[NFRAG];   // channel offset of this fragment within out[l]
    int C_l[NFRAG];        // total channels in out[l] (= 256*cnt_l)
    int cg_off[NFRAG];     // offset into g_cg
};

// CG coefficient storage (sum over triples of (2l+1)*(2l1+1) = 3977 floats)
__device__ float g_cg[4096];

// Exact factorials 0..16 (all exactly representable in double)
__constant__ double c_fact[17] = {
    1.0, 1.0, 2.0, 6.0, 24.0, 120.0, 720.0, 5040.0, 40320.0, 362880.0,
    3628800.0, 39916800.0, 479001600.0, 6227020800.0, 87178291200.0,
    1307674368000.0, 20922789888000.0
};

#define FX_L1(F,L1,L2,L) L1,
#define FX_L2(F,L1,L2,L) L2,
#define FX_LO(F,L1,L2,L) L,
__constant__ int c_fl1[NFRAG] = { FRAGS(FX_L1) };
__constant__ int c_fl2[NFRAG] = { FRAGS(FX_L2) };
__constant__ int c_flo[NFRAG] = { FRAGS(FX_LO) };

// ---------------------------------------------------------------------------
// CG coefficient (Condon-Shortley), exact fp64 factorial arithmetic.
// ---------------------------------------------------------------------------
__device__ float cg_coef(int l1, int l2, int l, int m1, int m2) {
    int m = m1 + m2;
    if (abs(m) > l || l < abs(l1 - l2) || l > l1 + l2) return 0.0f;
    double pref = (double)(2 * l + 1)
        * c_fact[l + l1 - l2] * c_fact[l - l1 + l2] * c_fact[l1 + l2 - l]
        / c_fact[l1 + l2 + l + 1];
    pref *= c_fact[l + m] * c_fact[l - m]
          * c_fact[l1 - m1] * c_fact[l1 + m1]
          * c_fact[l2 - m2] * c_fact[l2 + m2];
    int kmin = max(0, max(-(l - l2 + m1), -(l - l1 - m2)));
    int kmax = min(l1 + l2 - l, min(l1 - m1, l2 + m2));
    double s = 0.0;
    for (int k = kmin; k <= kmax; k++) {
        double d = c_fact[k] * c_fact[l1 + l2 - l - k] * c_fact[l1 - m1 - k]
                 * c_fact[l2 + m2 - k] * c_fact[l - l2 + m1 + k]
                 * c_fact[l - l1 - m2 + k];
        s += (k & 1) ? (-1.0 / d) : (1.0 / d);
    }
    return (float)(sqrt(pref) * s);
}

// Init kernel: one block per fragment fills its rectangular CG table
// layout: cg[m_idx * (2*l1+1) + (m1+l1)]
__global__ void init_cg_kernel(Meta meta) {
    int f = blockIdx.x;
    int l1 = c_fl1[f], l2 = c_fl2[f], l = c_flo[f];
    int D1 = 2 * l1 + 1, D = 2 * l + 1;
    int n = D * D1;
    for (int e = threadIdx.x; e < n; e += blockDim.x) {
        int mi = e / D1, k1 = e % D1;
        int m1 = k1 - l1;
        int m  = mi - l;
        int m2 = m - m1;
        float v = 0.0f;
        if (m2 >= -l2 && m2 <= l2) v = cg_coef(l1, l2, l, m1, m2);
        g_cg[meta.cg_off[f] + e] = v;
    }
}

// ---------------------------------------------------------------------------
// Per-triple body: fully unrolled, a1/a2/accumulators in registers.
// thread t = channel pair (i = t>>4, j = t&15) for one batch b.
// ---------------------------------------------------------------------------
template <int L1, int L2, int L>
__device__ __forceinline__ void frag_body(
    const float2* __restrict__ act1, const float2* __restrict__ act2,
    float2* __restrict__ out, const float* __restrict__ cg,
    int b, int C_l, int chan_off, int out_base, float2* sh_out)
{
    constexpr int D1 = 2 * L1 + 1;
    constexpr int D2 = 2 * L2 + 1;
    constexpr int D  = 2 * L + 1;

    const int t = threadIdx.x;
    const int i = t >> 4;
    const int j = t & 15;

    float2 a1[D1], a2[D2];
    const float2* p1 = act1 + (b * 16 + i) * D1;
    const float2* p2 = act2 + (b * 16 + j) * D2;
#pragma unroll
    for (int k = 0; k < D1; k++) a1[k] = __ldg(p1 + k);
#pragma unroll
    for (int k = 0; k < D2; k++) a2[k] = __ldg(p2 + k);

#pragma unroll
    for (int mi = 0; mi < D; ++mi) {
        float re = 0.0f, im = 0.0f;
#pragma unroll
        for (int k1 = 0; k1 < D1; ++k1) {
            const int m1 = k1 - L1;
            const int m2 = (mi - L) - m1;          // constant after unroll
            if (m2 >= -L2 && m2 <= L2) {           // folds at compile time
                const float C = __ldg(cg + mi * D1 + k1);
                const float2 v1 = a1[k1];
                const float2 v2 = a2[m2 + L2];
                const float cx1 = C * v1.x;
                const float cy1 = C * v1.y;
                re = fmaf(cx1, v2.x, re);
                re = fmaf(-cy1, v2.y, re);
                im = fmaf(cx1, v2.y, im);
                im = fmaf(cy1, v2.x, im);
            }
        }
        sh_out[t * D + mi] = make_float2(re, im);
    }
    __syncthreads();

    // Coalesced copy-out: fragment-batch region is a contiguous run of
    // 256*D float2 in the output tensor.
    float2* dst = out + out_base + (size_t)(b * C_l + chan_off) * D;
#pragma unroll
    for (int r = 0; r < D; r++) {
        dst[r * 256 + t] = sh_out[r * 256 + t];
    }
}

__global__ void __launch_bounds__(256) cg_main_kernel(
    const float* __restrict__ a0, const float* __restrict__ a1,
    const float* __restrict__ a2, const float* __restrict__ a3,
    const float* __restrict__ a4, const float* __restrict__ a5,
    float2* __restrict__ out, Meta meta)
{
    __shared__ float2 sh_out[256 * 11];
    const int f = blockIdx.y;
    const int b = blockIdx.x;

    switch (f) {
#define FCASE(F,L1,L2,L)                                                      \
    case F:                                                                   \
        frag_body<L1, L2, L>((const float2*)a##L1, (const float2*)a##L2, out, \
                             g_cg + meta.cg_off[F], b, meta.C_l[F],           \
                             meta.chan_off[F], meta.out_base[F], sh_out);     \
        break;
    FRAGS(FCASE)
#undef FCASE
    default: break;
    }
}

// ---------------------------------------------------------------------------
// Host side
// ---------------------------------------------------------------------------
#define FX_HT(F,L1,L2,L) {L1, L2, L},
static const int h_tr[NFRAG][3] = { FRAGS(FX_HT) };

extern "C" void kernel_launch(void* const* d_in, const int* in_sizes, int n_in,
                              void* d_out, int out_size)
{
    (void)in_sizes; (void)n_in; (void)out_size;

    Meta meta;
    int cnt[6] = {0, 0, 0, 0, 0, 0};
    for (int f = 0; f < NFRAG; f++) cnt[h_tr[f][2]]++;

    long long base[7];
    base[0] = 0;
    for (int l = 0; l < 6; l++)
        base[l + 1] = base[l] + 256LL * 256 * cnt[l] * (2 * l + 1);

    int idx[6] = {0, 0, 0, 0, 0, 0};
    int cgo = 0;
    for (int f = 0; f < NFRAG; f++) {
        const int l1 = h_tr[f][0];
        const int l  = h_tr[f][2];
        meta.out_base[f] = (int)base[l];
        meta.chan_off[f] = 256 * idx[l];
        idx[l]++;
        meta.C_l[f]  = 256 * cnt[l];
        meta.cg_off[f] = cgo;
        cgo += (2 * l + 1) * (2 * l1 + 1);
    }

    init_cg_kernel<<<NFRAG, 128>>>(meta);

    cg_main_kernel<<<dim3(256, NFRAG), 256>>>(
        (const float*)d_in[0], (const float*)d_in[1], (const float*)d_in[2],
        (const float*)d_in[3], (const float*)d_in[4], (const float*)d_in[5],
        (float2*)d_out, meta);
}

// round 2
// speedup vs baseline: 1.1701x; 1.1701x over previous
#include <cuda_runtime.h>

// ============================================================================
// Clebsch-Gordan tensor product, MAXL=5, TAUS=16, BATCH=256.
// R2: compile-time CG tables (no init kernel, no CG loads), conflict-free
//     re/im SMEM planes, heavy-fragment-first block scheduling.
// ============================================================================

#define NFRAG 69

// X-macro: (frag_id, l1, l2, l) in exact reference _TRIPLES order
#define FRAGS(X) \
X(0,0,0,0) X(1,1,0,1) X(2,1,1,0) X(3,1,1,1) X(4,1,1,2) \
X(5,2,0,2) X(6,2,1,1) X(7,2,1,2) X(8,2,1,3) \
X(9,2,2,0) X(10,2,2,1) X(11,2,2,2) X(12,2,2,3) X(13,2,2,4) \
X(14,3,0,3) X(15,3,1,2) X(16,3,1,3) X(17,3,1,4) \
X(18,3,2,1) X(19,3,2,2) X(20,3,2,3) X(21,3,2,4) X(22,3,2,5) \
X(23,3,3,0) X(24,3,3,1) X(25,3,3,2) X(26,3,3,3) X(27,3,3,4) X(28,3,3,5) \
X(29,4,0,4) X(30,4,1,3) X(31,4,1,4) X(32,4,1,5) \
X(33,4,2,2) X(34,4,2,3) X(35,4,2,4) X(36,4,2,5) \
X(37,4,3,1) X(38,4,3,2) X(39,4,3,3) X(40,4,3,4) X(41,4,3,5) \
X(42,4,4,0) X(43,4,4,1) X(44,4,4,2) X(45,4,4,3) X(46,4,4,4) X(47,4,4,5) \
X(48,5,0,5) X(49,5,1,4) X(50,5,1,5) \
X(51,5,2,3) X(52,5,2,4) X(53,5,2,5) \
X(54,5,3,2) X(55,5,3,3) X(56,5,3,4) X(57,5,3,5) \
X(58,5,4,1) X(59,5,4,2) X(60,5,4,3) X(61,5,4,4) X(62,5,4,5) \
X(63,5,5,0) X(64,5,5,1) X(65,5,5,2) X(66,5,5,3) X(67,5,5,4) X(68,5,5,5)

struct Meta {
    int order[NFRAG];      // blockIdx.y -> fragment id (heavy-first)
    int out_base[NFRAG];   // float2 offset of out[l] section start
    int chan_off[NFRAG];   // channel offset of this fragment within out[l]
    int C_l[NFRAG];        // total channels in out[l] (= 256*cnt_l)
};

// ---------------------------------------------------------------------------
// Compile-time CG coefficients (exact fp64 factorials, Newton sqrt).
// ---------------------------------------------------------------------------
__host__ __device__ constexpr double cfact(int n) {
    double r = 1.0;
    for (int i = 2; i <= n; i++) r *= (double)i;
    return r;
}
__host__ __device__ constexpr double csqrt(double x) {
    if (x <= 0.0) return 0.0;
    double g = x > 1.0 ? x : 1.0;
    for (int i = 0; i < 200; i++) g = 0.5 * (g + x / g);
    return g;
}
__host__ __device__ constexpr double cg_cd(int l1, int l2, int l, int m1, int m2) {
    int m = m1 + m2;
    if (m < -l || m > l) return 0.0;
    if (l < (l1 > l2 ? l1 - l2 : l2 - l1) || l > l1 + l2) return 0.0;
    double pref = (double)(2 * l + 1)
        * cfact(l + l1 - l2) * cfact(l - l1 + l2) * cfact(l1 + l2 - l)
        / cfact(l1 + l2 + l + 1);
    pref *= cfact(l + m) * cfact(l - m)
          * cfact(l1 - m1) * cfact(l1 + m1)
          * cfact(l2 - m2) * cfact(l2 + m2);
    int kmin = 0;
    if (-(l - l2 + m1) > kmin) kmin = -(l - l2 + m1);
    if (-(l - l1 - m2) > kmin) kmin = -(l - l1 - m2);
    int kmax = l1 + l2 - l;
    if (l1 - m1 < kmax) kmax = l1 - m1;
    if (l2 + m2 < kmax) kmax = l2 + m2;
    double s = 0.0;
    for (int k = kmin; k <= kmax; k++) {
        double d = cfact(k) * cfact(l1 + l2 - l - k) * cfact(l1 - m1 - k)
                 * cfact(l2 + m2 - k) * cfact(l - l2 + m1 + k)
                 * cfact(l - l1 - m2 + k);
        s += (k & 1) ? (-1.0 / d) : (1.0 / d);
    }
    return csqrt(pref) * s;
}

template <int L1, int L2, int L>
struct CGTab {
    float c[2 * L + 1][2 * L1 + 1];
    constexpr CGTab() : c() {
        for (int mi = 0; mi < 2 * L + 1; mi++)
            for (int k1 = 0; k1 < 2 * L1 + 1; k1++) {
                int m1 = k1 - L1;
                int m2 = (mi - L) - m1;
                c[mi][k1] = (m2 >= -L2 && m2 <= L2)
                          ? (float)cg_cd(L1, L2, L, m1, m2) : 0.0f;
            }
    }
};
template <int L1, int L2, int L>
__device__ constexpr CGTab<L1, L2, L> g_tab{};

// ---------------------------------------------------------------------------
// Per-triple body: fully unrolled; a1/a2 in registers; CG as constants.
// thread t = channel pair (i = t>>4, j = t&15) for one batch b.
// Staging: separate re/im float planes, word-stride D (odd -> conflict-free).
// ---------------------------------------------------------------------------
template <int L1, int L2, int L>
__device__ __forceinline__ void frag_body(
    const float2* __restrict__ act1, const float2* __restrict__ act2,
    float2* __restrict__ out,
    int b, int C_l, int chan_off, int out_base,
    float* sre, float* sim)
{
    constexpr int D1 = 2 * L1 + 1;
    constexpr int D2 = 2 * L2 + 1;
    constexpr int D  = 2 * L + 1;

    const int t = threadIdx.x;
    const int i = t >> 4;
    const int j = t & 15;

    float2 a1[D1], a2[D2];
    const float2* p1 = act1 + (b * 16 + i) * D1;
    const float2* p2 = act2 + (b * 16 + j) * D2;
#pragma unroll
    for (int k = 0; k < D1; k++) a1[k] = __ldg(p1 + k);
#pragma unroll
    for (int k = 0; k < D2; k++) a2[k] = __ldg(p2 + k);

    float2* dst = out + out_base + (size_t)(b * C_l + chan_off) * D;

#pragma unroll
    for (int mi = 0; mi < D; ++mi) {
        float re = 0.0f, im = 0.0f;
#pragma unroll
        for (int k1 = 0; k1 < D1; ++k1) {
            const int m1 = k1 - L1;
            const int m2 = (mi - L) - m1;          // constant after unroll
            if (m2 >= -L2 && m2 <= L2) {           // folds at compile time
                const float C = g_tab<L1, L2, L>.c[mi][k1];
                const float2 v1 = a1[k1];
                const float2 v2 = a2[m2 + L2];
                const float cx1 = C * v1.x;
                const float cy1 = C * v1.y;
                re = fmaf(cx1, v2.x, re);
                re = fmaf(-cy1, v2.y, re);
                im = fmaf(cx1, v2.y, im);
                im = fmaf(cy1, v2.x, im);
            }
        }
        if (D == 1) {
            // identity mapping: direct coalesced store, no SMEM
            dst[t] = make_float2(re, im);
        } else {
            sre[t * D + mi] = re;
            sim[t * D + mi] = im;
        }
    }
    if (D == 1) return;
    __syncthreads();

    // Coalesced copy-out: fragment-batch region is a contiguous run of
    // 256*D float2; planes are read at consecutive word addresses.
#pragma unroll
    for (int r = 0; r < D; r++) {
        const int e = r * 256 + t;
        dst[e] = make_float2(sre[e], sim[e]);
    }
}

__global__ void __launch_bounds__(256) cg_main_kernel(
    const float* __restrict__ a0, const float* __restrict__ a1,
    const float* __restrict__ a2, const float* __restrict__ a3,
    const float* __restrict__ a4, const float* __restrict__ a5,
    float2* __restrict__ out, Meta meta)
{
    __shared__ float sre[256 * 11];
    __shared__ float sim[256 * 11];
    const int f = meta.order[blockIdx.y];
    const int b = blockIdx.x;

    switch (f) {
#define FCASE(F,L1,L2,L)                                                      \
    case F:                                                                   \
        frag_body<L1, L2, L>((const float2*)a##L1, (const float2*)a##L2, out, \
                             b, meta.C_l[F], meta.chan_off[F],                \
                             meta.out_base[F], sre, sim);                     \
        break;
    FRAGS(FCASE)
#undef FCASE
    default: break;
    }
}

// ---------------------------------------------------------------------------
// Host side
// ---------------------------------------------------------------------------
#define FX_HT(F,L1,L2,L) {L1, L2, L},
static const int h_tr[NFRAG][3] = { FRAGS(FX_HT) };

extern "C" void kernel_launch(void* const* d_in, const int* in_sizes, int n_in,
                              void* d_out, int out_size)
{
    (void)in_sizes; (void)n_in; (void)out_size;

    Meta meta;
    int cnt[6] = {0, 0, 0, 0, 0, 0};
    for (int f = 0; f < NFRAG; f++) cnt[h_tr[f][2]]++;

    long long base[7];
    base[0] = 0;
    for (int l = 0; l < 6; l++)
        base[l + 1] = base[l] + 256LL * 256 * cnt[l] * (2 * l + 1);

    int idx[6] = {0, 0, 0, 0, 0, 0};
    for (int f = 0; f < NFRAG; f++) {
        const int l = h_tr[f][2];
        meta.out_base[f] = (int)base[l];
        meta.chan_off[f] = 256 * idx[l];
        idx[l]++;
        meta.C_l[f] = 256 * cnt[l];
    }

    // Heavy-first schedule: fragments sorted by descending output degree D.
    int pos = 0;
    for (int l = 5; l >= 0; l--)
        for (int f = 0; f < NFRAG; f++)
            if (h_tr[f][2] == l) meta.order[pos++] = f;

    cg_main_kernel<<<dim3(256, NFRAG), 256>>>(
        (const float*)d_in[0], (const float*)d_in[1], (const float*)d_in[2],
        (const float*)d_in[3], (const float*)d_in[4], (const float*)d_in[5],
        (float2*)d_out, meta);
}

// round 3
// speedup vs baseline: 1.2287x; 1.0500x over previous
#include <cuda_runtime.h>

// ============================================================================
// Clebsch-Gordan tensor product, MAXL=5, TAUS=16, BATCH=256.
// R3: register-diet contraction (a2-resident, a1 streamed, mi-tiled
//     accumulators) under __launch_bounds__(256,5) for 62.5% occupancy;
//     single interleaved SMEM plane + float4 copy-out.
// ============================================================================

#define NFRAG 69

// X-macro: (frag_id, l1, l2, l) in exact reference _TRIPLES order
#define FRAGS(X) \
X(0,0,0,0) X(1,1,0,1) X(2,1,1,0) X(3,1,1,1) X(4,1,1,2) \
X(5,2,0,2) X(6,2,1,1) X(7,2,1,2) X(8,2,1,3) \
X(9,2,2,0) X(10,2,2,1) X(11,2,2,2) X(12,2,2,3) X(13,2,2,4) \
X(14,3,0,3) X(15,3,1,2) X(16,3,1,3) X(17,3,1,4) \
X(18,3,2,1) X(19,3,2,2) X(20,3,2,3) X(21,3,2,4) X(22,3,2,5) \
X(23,3,3,0) X(24,3,3,1) X(25,3,3,2) X(26,3,3,3) X(27,3,3,4) X(28,3,3,5) \
X(29,4,0,4) X(30,4,1,3) X(31,4,1,4) X(32,4,1,5) \
X(33,4,2,2) X(34,4,2,3) X(35,4,2,4) X(36,4,2,5) \
X(37,4,3,1) X(38,4,3,2) X(39,4,3,3) X(40,4,3,4) X(41,4,3,5) \
X(42,4,4,0) X(43,4,4,1) X(44,4,4,2) X(45,4,4,3) X(46,4,4,4) X(47,4,4,5) \
X(48,5,0,5) X(49,5,1,4) X(50,5,1,5) \
X(51,5,2,3) X(52,5,2,4) X(53,5,2,5) \
X(54,5,3,2) X(55,5,3,3) X(56,5,3,4) X(57,5,3,5) \
X(58,5,4,1) X(59,5,4,2) X(60,5,4,3) X(61,5,4,4) X(62,5,4,5) \
X(63,5,5,0) X(64,5,5,1) X(65,5,5,2) X(66,5,5,3) X(67,5,5,4) X(68,5,5,5)

struct Meta {
    int order[NFRAG];      // blockIdx.y -> fragment id (heavy-first)
    int out_base[NFRAG];   // float2 offset of out[l] section start
    int chan_off[NFRAG];   // channel offset of this fragment within out[l]
    int C_l[NFRAG];        // total channels in out[l] (= 256*cnt_l)
};

// ---------------------------------------------------------------------------
// Compile-time CG coefficients (exact fp64 factorials, Newton sqrt).
// ---------------------------------------------------------------------------
__host__ __device__ constexpr double cfact(int n) {
    double r = 1.0;
    for (int i = 2; i <= n; i++) r *= (double)i;
    return r;
}
__host__ __device__ constexpr double csqrt(double x) {
    if (x <= 0.0) return 0.0;
    double g = x > 1.0 ? x : 1.0;
    for (int i = 0; i < 200; i++) g = 0.5 * (g + x / g);
    return g;
}
__host__ __device__ constexpr double cg_cd(int l1, int l2, int l, int m1, int m2) {
    int m = m1 + m2;
    if (m < -l || m > l) return 0.0;
    if (l < (l1 > l2 ? l1 - l2 : l2 - l1) || l > l1 + l2) return 0.0;
    double pref = (double)(2 * l + 1)
        * cfact(l + l1 - l2) * cfact(l - l1 + l2) * cfact(l1 + l2 - l)
        / cfact(l1 + l2 + l + 1);
    pref *= cfact(l + m) * cfact(l - m)
          * cfact(l1 - m1) * cfact(l1 + m1)
          * cfact(l2 - m2) * cfact(l2 + m2);
    int kmin = 0;
    if (-(l - l2 + m1) > kmin) kmin = -(l - l2 + m1);
    if (-(l - l1 - m2) > kmin) kmin = -(l - l1 - m2);
    int kmax = l1 + l2 - l;
    if (l1 - m1 < kmax) kmax = l1 - m1;
    if (l2 + m2 < kmax) kmax = l2 + m2;
    double s = 0.0;
    for (int k = kmin; k <= kmax; k++) {
        double d = cfact(k) * cfact(l1 + l2 - l - k) * cfact(l1 - m1 - k)
                 * cfact(l2 + m2 - k) * cfact(l - l2 + m1 + k)
                 * cfact(l - l1 - m2 + k);
        s += (k & 1) ? (-1.0 / d) : (1.0 / d);
    }
    return csqrt(pref) * s;
}

template <int L1, int L2, int L>
struct CGTab {
    float c[2 * L + 1][2 * L1 + 1];
    constexpr CGTab() : c() {
        for (int mi = 0; mi < 2 * L + 1; mi++)
            for (int k1 = 0; k1 < 2 * L1 + 1; k1++) {
                int m1 = k1 - L1;
                int m2 = (mi - L) - m1;
                c[mi][k1] = (m2 >= -L2 && m2 <= L2)
                          ? (float)cg_cd(L1, L2, L, m1, m2) : 0.0f;
            }
    }
};
template <int L1, int L2, int L>
__device__ constexpr CGTab<L1, L2, L> g_tab{};

// ---------------------------------------------------------------------------
// Per-triple body. thread t = channel pair (i = t>>4, j = t&15), batch b.
// a2 row resident in registers; a1 streamed per k1 (L1-hit broadcast loads);
// mi accumulators tiled to bound register pressure.
// Staging: interleaved float2 plane, word-stride 2D (conflict-free, D odd),
// copy-out as float4.
// ---------------------------------------------------------------------------
template <int L1, int L2, int L>
__device__ __forceinline__ void frag_body(
    const float2* __restrict__ act1, const float2* __restrict__ act2,
    float2* __restrict__ out,
    int b, int C_l, int chan_off, int out_base, float2* sh)
{
    constexpr int D1 = 2 * L1 + 1;
    constexpr int D2 = 2 * L2 + 1;
    constexpr int D  = 2 * L + 1;
    // accumulator tile: keep 2*D2 + 2*TILE + 2 data regs ~<= 34
    constexpr int TILE0 = 16 - D2 < 3 ? 3 : 16 - D2;
    constexpr int TILE  = TILE0 > D ? D : TILE0;
    constexpr int NT    = (D + TILE - 1) / TILE;

    const int t = threadIdx.x;
    const int i = t >> 4;
    const int j = t & 15;

    float2 a2[D2];
    const float2* p2 = act2 + (b * 16 + j) * D2;
#pragma unroll
    for (int k = 0; k < D2; k++) a2[k] = __ldg(p2 + k);

    const float2* p1 = act1 + (b * 16 + i) * D1;
    float2* dst = out + out_base + (size_t)(b * C_l + chan_off) * D;

    if (D == 1) {
        // identity mapping: direct coalesced store, no SMEM
        float re = 0.0f, im = 0.0f;
#pragma unroll
        for (int k1 = 0; k1 < D1; ++k1) {
            const int k2 = -L - (k1 - L1) + L2;   // mi = 0
            if (k2 >= 0 && k2 < D2) {
                const float C = g_tab<L1, L2, L>.c[0][k1];
                const float2 v1 = __ldg(p1 + k1);
                const float2 v2 = a2[k2];
                const float cx = C * v1.x, cy = C * v1.y;
                re = fmaf(cx, v2.x, re); re = fmaf(-cy, v2.y, re);
                im = fmaf(cx, v2.y, im); im = fmaf(cy, v2.x, im);
            }
        }
        dst[t] = make_float2(re, im);
        return;
    }

#pragma unroll
    for (int tile = 0; tile < NT; ++tile) {
        float ar[TILE], ai[TILE];
#pragma unroll
        for (int u = 0; u < TILE; ++u) { ar[u] = 0.0f; ai[u] = 0.0f; }
#pragma unroll
        for (int k1 = 0; k1 < D1; ++k1) {
            // does any mi in this tile touch this k1?  (compile-time)
            bool any = false;
#pragma unroll
            for (int u = 0; u < TILE; ++u) {
                const int mi = tile * TILE + u;
                const int k2 = (mi - L) - (k1 - L1) + L2;
                if (mi < D && k2 >= 0 && k2 < D2) any = true;
            }
            if (!any) continue;
            const float2 v1 = __ldg(p1 + k1);
#pragma unroll
            for (int u = 0; u < TILE; ++u) {
                const int mi = tile * TILE + u;
                const int k2 = (mi - L) - (k1 - L1) + L2;
                if (mi < D && k2 >= 0 && k2 < D2) {
                    const float C = g_tab<L1, L2, L>.c[mi][k1];
                    const float2 v2 = a2[k2];
                    const float cx = C * v1.x, cy = C * v1.y;
                    ar[u] = fmaf(cx, v2.x, ar[u]);
                    ar[u] = fmaf(-cy, v2.y, ar[u]);
                    ai[u] = fmaf(cx, v2.y, ai[u]);
                    ai[u] = fmaf(cy, v2.x, ai[u]);
                }
            }
        }
#pragma unroll
        for (int u = 0; u < TILE; ++u) {
            const int mi = tile * TILE + u;
            if (mi < D) sh[t * D + mi] = make_float2(ar[u], ai[u]);
        }
    }
    __syncthreads();

    // Coalesced float4 copy-out: block region = 256*D contiguous float2
    // = 128*D float4 (16B-aligned: all offsets even in float2 units).
    float4* dst4 = reinterpret_cast<float4*>(dst);
    const float4* sh4 = reinterpret_cast<const float4*>(sh);
#pragma unroll
    for (int e = t; e < 128 * D; e += 256) {
        dst4[e] = sh4[e];
    }
}

__global__ void __launch_bounds__(256, 5) cg_main_kernel(
    const float* __restrict__ a0, const float* __restrict__ a1,
    const float* __restrict__ a2, const float* __restrict__ a3,
    const float* __restrict__ a4, const float* __restrict__ a5,
    float2* __restrict__ out, Meta meta)
{
    __shared__ alignas(16) float2 sh[256 * 11];
    const int f = meta.order[blockIdx.y];
    const int b = blockIdx.x;

    switch (f) {
#define FCASE(F,L1,L2,L)                                                      \
    case F:                                                                   \
        frag_body<L1, L2, L>((const float2*)a##L1, (const float2*)a##L2, out, \
                             b, meta.C_l[F], meta.chan_off[F],                \
                             meta.out_base[F], sh);                           \
        break;
    FRAGS(FCASE)
#undef FCASE
    default: break;
    }
}

// ---------------------------------------------------------------------------
// Host side
// ---------------------------------------------------------------------------
#define FX_HT(F,L1,L2,L) {L1, L2, L},
static const int h_tr[NFRAG][3] = { FRAGS(FX_HT) };

extern "C" void kernel_launch(void* const* d_in, const int* in_sizes, int n_in,
                              void* d_out, int out_size)
{
    (void)in_sizes; (void)n_in; (void)out_size;

    Meta meta;
    int cnt[6] = {0, 0, 0, 0, 0, 0};
    for (int f = 0; f < NFRAG; f++) cnt[h_tr[f][2]]++;

    long long base[7];
    base[0] = 0;
    for (int l = 0; l < 6; l++)
        base[l + 1] = base[l] + 256LL * 256 * cnt[l] * (2 * l + 1);

    int idx[6] = {0, 0, 0, 0, 0, 0};
    for (int f = 0; f < NFRAG; f++) {
        const int l = h_tr[f][2];
        meta.out_base[f] = (int)base[l];
        meta.chan_off[f] = 256 * idx[l];
        idx[l]++;
        meta.C_l[f] = 256 * cnt[l];
    }

    // Heavy-first schedule: fragments sorted by descending output degree D.
    int pos = 0;
    for (int l = 5; l >= 0; l--)
        for (int f = 0; f < NFRAG; f++)
            if (h_tr[f][2] == l) meta.order[pos++] = f;

    cg_main_kernel<<<dim3(256, NFRAG), 256>>>(
        (const float*)d_in[0], (const float*)d_in[1], (const float*)d_in[2],
        (const float*)d_in[3], (const float*)d_in[4], (const float*)d_in[5],
        (float2*)d_out, meta);
}

// round 4
// speedup vs baseline: 1.6111x; 1.3113x over previous
#include <cuda_runtime.h>

// ============================================================================
// Clebsch-Gordan tensor product, MAXL=5, TAUS=16, BATCH=256.
// R4: merge all output-l fragments of each (l1,l2) pair into one block
//     (products u,v shared across l; CG weights are compile-time immediates),
//     split into l-groups so SMEM staging stays <= 43KB (5 CTAs/SM).
//     32 groups total, all output offsets compile-time.
// ============================================================================

#define NGRP 32
// X(G, L1, L2, LA, LB): block handles outputs l in [LA..LB] of pair (L1,L2).
// Heavy-first order.
#define GROUPS(X) \
X(0,3,1,2,4)  X(1,5,5,4,5)  X(2,5,4,4,5)  X(3,5,3,4,5)  X(4,5,2,4,5) \
X(5,5,1,4,5)  X(6,4,4,4,5)  X(7,4,3,4,5)  X(8,4,2,4,5)  X(9,4,1,4,5) \
X(10,3,3,4,5) X(11,3,2,4,5) X(12,5,5,0,3) X(13,4,4,0,3) X(14,3,3,0,3) \
X(15,2,2,3,4) X(16,5,4,1,3) X(17,4,3,1,3) X(18,3,2,1,3) X(19,2,1,1,3) \
X(20,5,3,2,3) X(21,4,2,2,3) X(22,5,0,5,5) X(23,4,0,4,4) X(24,2,2,0,2) \
X(25,1,1,0,2) X(26,5,2,3,3) X(27,4,1,3,3) X(28,3,0,3,3) X(29,2,0,2,2) \
X(30,1,0,1,1) X(31,0,0,0,0)

// ---------------------------------------------------------------------------
// Compile-time CG coefficients (exact fp64 factorials, Newton sqrt).
// ---------------------------------------------------------------------------
__host__ __device__ constexpr double cfact(int n) {
    double r = 1.0;
    for (int i = 2; i <= n; i++) r *= (double)i;
    return r;
}
__host__ __device__ constexpr double csqrt(double x) {
    if (x <= 0.0) return 0.0;
    double g = x > 1.0 ? x : 1.0;
    for (int i = 0; i < 200; i++) g = 0.5 * (g + x / g);
    return g;
}
__host__ __device__ constexpr double cg_cd(int l1, int l2, int l, int m1, int m2) {
    int m = m1 + m2;
    if (m < -l || m > l) return 0.0;
    if (l < (l1 > l2 ? l1 - l2 : l2 - l1) || l > l1 + l2) return 0.0;
    double pref = (double)(2 * l + 1)
        * cfact(l + l1 - l2) * cfact(l - l1 + l2) * cfact(l1 + l2 - l)
        / cfact(l1 + l2 + l + 1);
    pref *= cfact(l + m) * cfact(l - m)
          * cfact(l1 - m1) * cfact(l1 + m1)
          * cfact(l2 - m2) * cfact(l2 + m2);
    int kmin = 0;
    if (-(l - l2 + m1) > kmin) kmin = -(l - l2 + m1);
    if (-(l - l1 - m2) > kmin) kmin = -(l - l1 - m2);
    int kmax = l1 + l2 - l;
    if (l1 - m1 < kmax) kmax = l1 - m1;
    if (l2 + m2 < kmax) kmax = l2 + m2;
    double s = 0.0;
    for (int k = kmin; k <= kmax; k++) {
        double d = cfact(k) * cfact(l1 + l2 - l - k) * cfact(l1 - m1 - k)
                 * cfact(l2 + m2 - k) * cfact(l - l2 + m1 + k)
                 * cfact(l - l1 - m2 + k);
        s += (k & 1) ? (-1.0 / d) : (1.0 / d);
    }
    return csqrt(pref) * s;
}

// ---------------------------------------------------------------------------
// Compile-time output layout (reference _TRIPLES order: l1 asc, l2 asc, l asc)
// ---------------------------------------------------------------------------
__host__ __device__ constexpr int LMX(int a) { return a > 5 ? 5 : a; }
__host__ __device__ constexpr int CNT(int l) {
    int c = 0;
    for (int l1 = 0; l1 <= 5; l1++)
        for (int l2 = 0; l2 <= l1; l2++)
            for (int lo = l1 - l2; lo <= LMX(l1 + l2); lo++)
                if (lo == l) c++;
    return c;
}
__host__ __device__ constexpr long BASE(int l) {   // float2 offset of out[l]
    long b = 0;
    for (int x = 0; x < l; x++) b += 65536L * CNT(x) * (2 * x + 1);
    return b;
}
__host__ __device__ constexpr int FIDX(int L1, int L2, int l) {
    int c = 0;
    for (int l1 = 0; l1 <= 5; l1++)
        for (int l2 = 0; l2 <= l1; l2++)
            for (int lo = l1 - l2; lo <= LMX(l1 + l2); lo++)
                if (lo == l) { if (l1 == L1 && l2 == L2) return c; c++; }
    return 0;
}

template <int L1, int L2, int LA, int LB>
struct GrpOff {
    static constexpr int NL = LB - LA + 1;
    long dbase[NL];   // out[l] section base (float2)
    long bstr[NL];    // per-batch stride = 256*CNT(l)*(2l+1)
    long coff[NL];    // fragment channel offset * (2l+1)
    int  sbase[NL];   // smem section base (float2)
    constexpr GrpOff() : dbase(), bstr(), coff(), sbase() {
        int off = 0;
        for (int lu = 0; lu < NL; lu++) {
            int l = LA + lu, D = 2 * l + 1;
            dbase[lu] = BASE(l);
            bstr[lu]  = 256L * CNT(l) * D;
            coff[lu]  = 256L * FIDX(L1, L2, l) * D;
            sbase[lu] = off;
            off += 256 * D;
        }
    }
};
template <int L1, int L2, int LA, int LB>
__device__ constexpr GrpOff<L1, L2, LA, LB> g_off{};

template <int L1, int L2, int LA, int LB>
struct CGSet {
    float c[LB - LA + 1][2 * LB + 1][2 * L1 + 1];
    constexpr CGSet() : c() {
        for (int lu = 0; lu <= LB - LA; lu++) {
            int l = LA + lu;
            for (int mi = 0; mi < 2 * l + 1; mi++)
                for (int k1 = 0; k1 < 2 * L1 + 1; k1++) {
                    int m1 = k1 - L1;
                    int m2 = (mi - l) - m1;
                    c[lu][mi][k1] = (m2 >= -L2 && m2 <= L2)
                                  ? (float)cg_cd(L1, L2, l, m1, m2) : 0.0f;
                }
        }
    }
};
template <int L1, int L2, int LA, int LB>
__device__ constexpr CGSet<L1, L2, LA, LB> g_cgs{};

// ---------------------------------------------------------------------------
// Group body. thread t = channel pair (i=t>>4, j=t&15), batch b.
// m outer, k1 inner: products u,v computed once, shared by all l >= |m| via
// FFMA with compile-time immediate CG weight. SMEM staging, float4 copy-out.
// ---------------------------------------------------------------------------
template <int L1, int L2, int LA, int LB>
__device__ __forceinline__ void grp_body(
    const float2* __restrict__ act1, const float2* __restrict__ act2,
    float2* __restrict__ out, int b, float2* __restrict__ sh)
{
    constexpr int D1 = 2 * L1 + 1;
    constexpr int D2 = 2 * L2 + 1;
    constexpr int NL = LB - LA + 1;
    constexpr bool RES1 = (2 * (D1 + D2) + 2 * NL) <= 36;  // a1 resident?

    const int t = threadIdx.x;
    const int i = t >> 4;
    const int j = t & 15;

    float2 a2r[D2];
    const float2* p2 = act2 + (b * 16 + j) * D2;
#pragma unroll
    for (int k = 0; k < D2; k++) a2r[k] = __ldg(p2 + k);

    const float2* p1 = act1 + (b * 16 + i) * D1;
    float2 a1r[RES1 ? D1 : 1];
    if (RES1) {
#pragma unroll
        for (int k = 0; k < D1; k++) a1r[k] = __ldg(p1 + k);
    }

#pragma unroll
    for (int m = -LB; m <= LB; m++) {
        const int absm = m < 0 ? -m : m;
        const int k1lo = (m + L1 - L2) > 0 ? (m + L1 - L2) : 0;
        const int k1hi = (m + L1 + L2) < (2 * L1) ? (m + L1 + L2) : (2 * L1);

        float aR[NL], aI[NL];
#pragma unroll
        for (int lu = 0; lu < NL; lu++) { aR[lu] = 0.0f; aI[lu] = 0.0f; }

#pragma unroll
        for (int k1 = k1lo; k1 <= k1hi; k1++) {
            const float2 v1 = RES1 ? a1r[k1] : __ldg(p1 + k1);
            const float2 v2 = a2r[m - (k1 - L1) + L2];
            const float u = fmaf(v1.x, v2.x, -(v1.y * v2.y));
            const float v = fmaf(v1.x, v2.y, v1.y * v2.x);
#pragma unroll
            for (int lu = 0; lu < NL; lu++) {
                const int l = LA + lu;
                if (l >= absm) {
                    const float C = g_cgs<L1, L2, LA, LB>.c[lu][m + l][k1];
                    if (C != 0.0f) {           // folds at compile time
                        aR[lu] = fmaf(C, u, aR[lu]);
                        aI[lu] = fmaf(C, v, aI[lu]);
                    }
                }
            }
        }
#pragma unroll
        for (int lu = 0; lu < NL; lu++) {
            const int l = LA + lu;
            if (l >= absm)
                sh[g_off<L1, L2, LA, LB>.sbase[lu] + t * (2 * l + 1) + (m + l)]
                    = make_float2(aR[lu], aI[lu]);
        }
    }
    __syncthreads();

    // Coalesced float4 copy-out per l section (each a contiguous 256*D float2)
#pragma unroll
    for (int lu = 0; lu < NL; lu++) {
        const int l = LA + lu, D = 2 * l + 1;
        float2* dst = out + g_off<L1, L2, LA, LB>.dbase[lu]
                    + (long)b * g_off<L1, L2, LA, LB>.bstr[lu]
                    + g_off<L1, L2, LA, LB>.coff[lu];
        float4* d4 = reinterpret_cast<float4*>(dst);
        const float4* s4 = reinterpret_cast<const float4*>(
            sh + g_off<L1, L2, LA, LB>.sbase[lu]);
#pragma unroll 4
        for (int e = t; e < 128 * D; e += 256) d4[e] = s4[e];
    }
}

__global__ void __launch_bounds__(256, 5) cg_main_kernel(
    const float* __restrict__ a0, const float* __restrict__ a1,
    const float* __restrict__ a2, const float* __restrict__ a3,
    const float* __restrict__ a4, const float* __restrict__ a5,
    float2* __restrict__ out)
{
    __shared__ alignas(16) float2 sh[21 * 256];   // max sum(2l+1)=21 -> 43KB
    const int b = blockIdx.x;

    switch (blockIdx.y) {
#define GCASE(G,L1,L2,LA,LB)                                                  \
    case G:                                                                   \
        grp_body<L1, L2, LA, LB>((const float2*)a##L1, (const float2*)a##L2,  \
                                 out, b, sh);                                 \
        break;
    GROUPS(GCASE)
#undef GCASE
    default: break;
    }
}

// ---------------------------------------------------------------------------
// Host side
// ---------------------------------------------------------------------------
extern "C" void kernel_launch(void* const* d_in, const int* in_sizes, int n_in,
                              void* d_out, int out_size)
{
    (void)in_sizes; (void)n_in; (void)out_size;

    cg_main_kernel<<<dim3(256, NGRP), 256>>>(
        (const float*)d_in[0], (const float*)d_in[1], (const float*)d_in[2],
        (const float*)d_in[3], (const float*)d_in[4], (const float*)d_in[5],
        (float2*)d_out);
}

// round 5
// speedup vs baseline: 1.7880x; 1.1098x over previous
#include <cuda_runtime.h>
#include <cstdint>

// ============================================================================
// Clebsch-Gordan tensor product, MAXL=5, TAUS=16, BATCH=256.
// R5: same merged (l1,l2)-group compute as R4, but copy-out is offloaded to
//     the TMA engine via cp.async.bulk (SMEM -> GMEM bulk_group). The SM only
//     issues STS for staging; LDS/STG disappear from the instruction stream.
// ============================================================================

#define NGRP 32
// X(G, L1, L2, LA, LB): block handles outputs l in [LA..LB] of pair (L1,L2).
// Heavy-first order.
#define GROUPS(X) \
X(0,3,1,2,4)  X(1,5,5,4,5)  X(2,5,4,4,5)  X(3,5,3,4,5)  X(4,5,2,4,5) \
X(5,5,1,4,5)  X(6,4,4,4,5)  X(7,4,3,4,5)  X(8,4,2,4,5)  X(9,4,1,4,5) \
X(10,3,3,4,5) X(11,3,2,4,5) X(12,5,5,0,3) X(13,4,4,0,3) X(14,3,3,0,3) \
X(15,2,2,3,4) X(16,5,4,1,3) X(17,4,3,1,3) X(18,3,2,1,3) X(19,2,1,1,3) \
X(20,5,3,2,3) X(21,4,2,2,3) X(22,5,0,5,5) X(23,4,0,4,4) X(24,2,2,0,2) \
X(25,1,1,0,2) X(26,5,2,3,3) X(27,4,1,3,3) X(28,3,0,3,3) X(29,2,0,2,2) \
X(30,1,0,1,1) X(31,0,0,0,0)

// ---------------------------------------------------------------------------
// Compile-time CG coefficients (exact fp64 factorials, Newton sqrt).
// ---------------------------------------------------------------------------
__host__ __device__ constexpr double cfact(int n) {
    double r = 1.0;
    for (int i = 2; i <= n; i++) r *= (double)i;
    return r;
}
__host__ __device__ constexpr double csqrt(double x) {
    if (x <= 0.0) return 0.0;
    double g = x > 1.0 ? x : 1.0;
    for (int i = 0; i < 200; i++) g = 0.5 * (g + x / g);
    return g;
}
__host__ __device__ constexpr double cg_cd(int l1, int l2, int l, int m1, int m2) {
    int m = m1 + m2;
    if (m < -l || m > l) return 0.0;
    if (l < (l1 > l2 ? l1 - l2 : l2 - l1) || l > l1 + l2) return 0.0;
    double pref = (double)(2 * l + 1)
        * cfact(l + l1 - l2) * cfact(l - l1 + l2) * cfact(l1 + l2 - l)
        / cfact(l1 + l2 + l + 1);
    pref *= cfact(l + m) * cfact(l - m)
          * cfact(l1 - m1) * cfact(l1 + m1)
          * cfact(l2 - m2) * cfact(l2 + m2);
    int kmin = 0;
    if (-(l - l2 + m1) > kmin) kmin = -(l - l2 + m1);
    if (-(l - l1 - m2) > kmin) kmin = -(l - l1 - m2);
    int kmax = l1 + l2 - l;
    if (l1 - m1 < kmax) kmax = l1 - m1;
    if (l2 + m2 < kmax) kmax = l2 + m2;
    double s = 0.0;
    for (int k = kmin; k <= kmax; k++) {
        double d = cfact(k) * cfact(l1 + l2 - l - k) * cfact(l1 - m1 - k)
                 * cfact(l2 + m2 - k) * cfact(l - l2 + m1 + k)
                 * cfact(l - l1 - m2 + k);
        s += (k & 1) ? (-1.0 / d) : (1.0 / d);
    }
    return csqrt(pref) * s;
}

// ---------------------------------------------------------------------------
// Compile-time output layout (reference _TRIPLES order: l1 asc, l2 asc, l asc)
// ---------------------------------------------------------------------------
__host__ __device__ constexpr int LMX(int a) { return a > 5 ? 5 : a; }
__host__ __device__ constexpr int CNT(int l) {
    int c = 0;
    for (int l1 = 0; l1 <= 5; l1++)
        for (int l2 = 0; l2 <= l1; l2++)
            for (int lo = l1 - l2; lo <= LMX(l1 + l2); lo++)
                if (lo == l) c++;
    return c;
}
__host__ __device__ constexpr long BASE(int l) {   // float2 offset of out[l]
    long b = 0;
    for (int x = 0; x < l; x++) b += 65536L * CNT(x) * (2 * x + 1);
    return b;
}
__host__ __device__ constexpr int FIDX(int L1, int L2, int l) {
    int c = 0;
    for (int l1 = 0; l1 <= 5; l1++)
        for (int l2 = 0; l2 <= l1; l2++)
            for (int lo = l1 - l2; lo <= LMX(l1 + l2); lo++)
                if (lo == l) { if (l1 == L1 && l2 == L2) return c; c++; }
    return 0;
}

template <int L1, int L2, int LA, int LB>
struct GrpOff {
    static constexpr int NL = LB - LA + 1;
    long dbase[NL];   // out[l] section base (float2)
    long bstr[NL];    // per-batch stride = 256*CNT(l)*(2l+1)
    long coff[NL];    // fragment channel offset * (2l+1)
    int  sbase[NL];   // smem section base (float2)
    constexpr GrpOff() : dbase(), bstr(), coff(), sbase() {
        int off = 0;
        for (int lu = 0; lu < NL; lu++) {
            int l = LA + lu, D = 2 * l + 1;
            dbase[lu] = BASE(l);
            bstr[lu]  = 256L * CNT(l) * D;
            coff[lu]  = 256L * FIDX(L1, L2, l) * D;
            sbase[lu] = off;
            off += 256 * D;
        }
    }
};
template <int L1, int L2, int LA, int LB>
__device__ constexpr GrpOff<L1, L2, LA, LB> g_off{};

template <int L1, int L2, int LA, int LB>
struct CGSet {
    float c[LB - LA + 1][2 * LB + 1][2 * L1 + 1];
    constexpr CGSet() : c() {
        for (int lu = 0; lu <= LB - LA; lu++) {
            int l = LA + lu;
            for (int mi = 0; mi < 2 * l + 1; mi++)
                for (int k1 = 0; k1 < 2 * L1 + 1; k1++) {
                    int m1 = k1 - L1;
                    int m2 = (mi - l) - m1;
                    c[lu][mi][k1] = (m2 >= -L2 && m2 <= L2)
                                  ? (float)cg_cd(L1, L2, l, m1, m2) : 0.0f;
                }
        }
    }
};
template <int L1, int L2, int LA, int LB>
__device__ constexpr CGSet<L1, L2, LA, LB> g_cgs{};

// ---------------------------------------------------------------------------
// Group body. thread t = channel pair (i=t>>4, j=t&15), batch b.
// m outer, k1 inner: products u,v computed once, shared by all l >= |m| via
// FFMA with compile-time immediate CG weight. SMEM staging; copy-out via
// cp.async.bulk (TMA engine) per l-section.
// ---------------------------------------------------------------------------
template <int L1, int L2, int LA, int LB>
__device__ __forceinline__ void grp_body(
    const float2* __restrict__ act1, const float2* __restrict__ act2,
    float2* __restrict__ out, int b, float2* __restrict__ sh)
{
    constexpr int D1 = 2 * L1 + 1;
    constexpr int D2 = 2 * L2 + 1;
    constexpr int NL = LB - LA + 1;
    constexpr bool RES1 = (2 * (D1 + D2) + 2 * NL) <= 36;  // a1 resident?

    const int t = threadIdx.x;
    const int i = t >> 4;
    const int j = t & 15;

    float2 a2r[D2];
    const float2* p2 = act2 + (b * 16 + j) * D2;
#pragma unroll
    for (int k = 0; k < D2; k++) a2r[k] = __ldg(p2 + k);

    const float2* p1 = act1 + (b * 16 + i) * D1;
    float2 a1r[RES1 ? D1 : 1];
    if (RES1) {
#pragma unroll
        for (int k = 0; k < D1; k++) a1r[k] = __ldg(p1 + k);
    }

#pragma unroll
    for (int m = -LB; m <= LB; m++) {
        const int absm = m < 0 ? -m : m;
        const int k1lo = (m + L1 - L2) > 0 ? (m + L1 - L2) : 0;
        const int k1hi = (m + L1 + L2) < (2 * L1) ? (m + L1 + L2) : (2 * L1);

        float aR[NL], aI[NL];
#pragma unroll
        for (int lu = 0; lu < NL; lu++) { aR[lu] = 0.0f; aI[lu] = 0.0f; }

#pragma unroll
        for (int k1 = k1lo; k1 <= k1hi; k1++) {
            const float2 v1 = RES1 ? a1r[k1] : __ldg(p1 + k1);
            const float2 v2 = a2r[m - (k1 - L1) + L2];
            const float u = fmaf(v1.x, v2.x, -(v1.y * v2.y));
            const float v = fmaf(v1.x, v2.y, v1.y * v2.x);
#pragma unroll
            for (int lu = 0; lu < NL; lu++) {
                const int l = LA + lu;
                if (l >= absm) {
                    const float C = g_cgs<L1, L2, LA, LB>.c[lu][m + l][k1];
                    if (C != 0.0f) {           // folds at compile time
                        aR[lu] = fmaf(C, u, aR[lu]);
                        aI[lu] = fmaf(C, v, aI[lu]);
                    }
                }
            }
        }
#pragma unroll
        for (int lu = 0; lu < NL; lu++) {
            const int l = LA + lu;
            if (l >= absm)
                sh[g_off<L1, L2, LA, LB>.sbase[lu] + t * (2 * l + 1) + (m + l)]
                    = make_float2(aR[lu], aI[lu]);
        }
    }
    __syncthreads();

    // TMA-engine copy-out: one bulk SMEM->GMEM copy per l-section.
    // All bases/sizes are 16B-aligned multiples (256*D float2, D odd, 256 even).
    if (t == 0) {
        asm volatile("fence.proxy.async.shared::cta;" ::: "memory");
#pragma unroll
        for (int lu = 0; lu < NL; lu++) {
            const int l = LA + lu, D = 2 * l + 1;
            float2* dst = out + g_off<L1, L2, LA, LB>.dbase[lu]
                        + (long)b * g_off<L1, L2, LA, LB>.bstr[lu]
                        + g_off<L1, L2, LA, LB>.coff[lu];
            uint32_t saddr;
            asm("{ .reg .u64 tt; cvta.to.shared.u64 tt, %1; cvt.u32.u64 %0, tt; }"
                : "=r"(saddr)
                : "l"(sh + g_off<L1, L2, LA, LB>.sbase[lu]));
            asm volatile(
                "cp.async.bulk.global.shared::cta.bulk_group [%0], [%1], %2;"
                :: "l"((unsigned long long)(uintptr_t)dst),
                   "r"(saddr), "r"(2048 * D)
                : "memory");
        }
        asm volatile("cp.async.bulk.commit_group;" ::: "memory");
        asm volatile("cp.async.bulk.wait_group 0;" ::: "memory");
    }
}

__global__ void __launch_bounds__(256, 5) cg_main_kernel(
    const float* __restrict__ a0, const float* __restrict__ a1,
    const float* __restrict__ a2, const float* __restrict__ a3,
    const float* __restrict__ a4, const float* __restrict__ a5,
    float2* __restrict__ out)
{
    __shared__ alignas(16) float2 sh[21 * 256];   // max sum(2l+1)=21 -> 43KB
    const int b = blockIdx.x;

    switch (blockIdx.y) {
#define GCASE(G,L1,L2,LA,LB)                                                  \
    case G:                                                                   \
        grp_body<L1, L2, LA, LB>((const float2*)a##L1, (const float2*)a##L2,  \
                                 out, b, sh);                                 \
        break;
    GROUPS(GCASE)
#undef GCASE
    default: break;
    }
}

// ---------------------------------------------------------------------------
// Host side
// ---------------------------------------------------------------------------
extern "C" void kernel_launch(void* const* d_in, const int* in_sizes, int n_in,
                              void* d_out, int out_size)
{
    (void)in_sizes; (void)n_in; (void)out_size;

    cg_main_kernel<<<dim3(256, NGRP), 256>>>(
        (const float*)d_in[0], (const float*)d_in[1], (const float*)d_in[2],
        (const float*)d_in[3], (const float*)d_in[4], (const float*)d_in[5],
        (float2*)d_out);
}